// round 5
// baseline (speedup 1.0000x reference)
#include <cuda_runtime.h>
#include <cuda_bf16.h>
#include <cstdint>

// RepeatEncoder: LIF spiking neuron over T=32 repeated presentations of the
// same frame. Input [B=64, C=64, L=512] fp32 -> output [B, T=32, L, C] fp32.
//
// Per (b,l,c): x = in[b,c,l]; v=0; for t in 0..31:
//   v = v + (x - v)/2;  s = (v >= 1) ? 1 : 0;  v = s ? 0 : v;  out[b,t,l,c] = s
//
// Write-bandwidth bound (256 MB out vs 8 MB in). Threads map c-fastest so the
// 32 stores per thread-group are perfectly coalesced; each thread owns 4
// consecutive c values and emits STG.128 per timestep.

namespace {
constexpr int B = 64;
constexpr int C = 64;
constexpr int L = 512;
constexpr int T = 32;
constexpr int C4 = C / 4;                  // float4 groups along channel dim
constexpr int TOTAL_THREADS = B * L * C4;  // 524288
}

__global__ void __launch_bounds__(256)
lif_repeat_encoder_kernel(const float* __restrict__ in, float* __restrict__ out) {
    const int idx = blockIdx.x * blockDim.x + threadIdx.x;
    if (idx >= TOTAL_THREADS) return;

    const int c4 = idx % C4;
    const int l  = (idx / C4) % L;
    const int b  = idx / (C4 * L);
    const int c  = c4 * 4;

    // Input is [B, C, L]: 4 strided scalar loads (stride L floats = 2KB).
    // Input totals 8 MB; this one-time gather is negligible vs 256 MB of writes.
    const float* xin = in + ((size_t)b * C + c) * L + l;
    const float x0 = xin[0 * L];
    const float x1 = xin[1 * L];
    const float x2 = xin[2 * L];
    const float x3 = xin[3 * L];

    float v0 = 0.f, v1 = 0.f, v2 = 0.f, v3 = 0.f;

    // Output is [B, T, L, C]; base for t=0 at this (b,l,c), stride L*C per t.
    float4* outp = reinterpret_cast<float4*>(
        out + ((size_t)b * T * L + l) * C + c);
    constexpr size_t strideT4 = (size_t)L * C / 4;  // float4 units per timestep

    #pragma unroll
    for (int t = 0; t < T; ++t) {
        // v = v + (x - v)/tau, tau = 2 (mul by 0.5 is exact == div by 2)
        v0 += (x0 - v0) * 0.5f;
        v1 += (x1 - v1) * 0.5f;
        v2 += (x2 - v2) * 0.5f;
        v3 += (x3 - v3) * 0.5f;

        const float s0 = (v0 >= 1.0f) ? 1.0f : 0.0f;
        const float s1 = (v1 >= 1.0f) ? 1.0f : 0.0f;
        const float s2 = (v2 >= 1.0f) ? 1.0f : 0.0f;
        const float s3 = (v3 >= 1.0f) ? 1.0f : 0.0f;

        // hard reset to 0 on spike
        v0 = (s0 != 0.0f) ? 0.0f : v0;
        v1 = (s1 != 0.0f) ? 0.0f : v1;
        v2 = (s2 != 0.0f) ? 0.0f : v2;
        v3 = (s3 != 0.0f) ? 0.0f : v3;

        outp[(size_t)t * strideT4] = make_float4(s0, s1, s2, s3);
    }
}

extern "C" void kernel_launch(void* const* d_in, const int* in_sizes, int n_in,
                              void* d_out, int out_size) {
    (void)in_sizes; (void)n_in; (void)out_size;
    const float* in = (const float*)d_in[0];
    float* out = (float*)d_out;

    const int threads = 256;
    const int blocks = (TOTAL_THREADS + threads - 1) / threads;  // 2048
    lif_repeat_encoder_kernel<<<blocks, threads>>>(in, out);
}

// round 6
// speedup vs baseline: 1.0351x; 1.0351x over previous
#include <cuda_runtime.h>
#include <cuda_bf16.h>
#include <cstdint>

// RepeatEncoder: LIF spiking neuron over T=32 repeated presentations of the
// same frame. Input [B=64, C=64, L=512] fp32 -> output [B, T=32, L, C] fp32.
//
// Per (b,l,c): x = in[b,c,l]; v=0; for t in 0..31:
//   v += (x - v)*0.5;  s = (v >= 1);  v = s ? 0 : v;  out[b,t,l,c] = s
//
// Write-bandwidth bound (256 MB out vs 8 MB in). R5 change: the input gather
// was 4 strided scalar LDGs per warp (32 lines each -> ~2.1M L1tex wavefronts,
// equal to the whole store stream). Now each 512-thread block stages its
// (b, 32-l, 64-c) input tile (8 KB) through shared memory with fully
// coalesced loads, then runs the identical coalesced STG.128 store loop.

namespace {
constexpr int B  = 64;
constexpr int C  = 64;
constexpr int L  = 512;
constexpr int T  = 32;
constexpr int LT = 32;                 // l-tile per block
constexpr int THREADS = 512;           // = LT * (C/4) compute units
constexpr int PITCH = LT + 1;          // smem pitch (33 floats) to limit conflicts
}

__global__ void __launch_bounds__(THREADS)
lif_repeat_encoder_kernel(const float* __restrict__ in, float* __restrict__ out) {
    __shared__ float tile[C * PITCH];  // tile[c][ll], pitch 33

    const int tid = threadIdx.x;
    const int bid = blockIdx.x;        // 0 .. B*(L/LT)-1 = 1023
    const int b   = bid >> 4;          // bid / (L/LT)
    const int l0  = (bid & 15) << 5;   // (bid % 16) * 32

    // ---- Coalesced load: input [B, C, L], this block needs [b, 0:64, l0:l0+32]
    // 4 iterations x 512 threads; each warp loads 32 consecutive floats (128B).
    {
        const int ll = tid & 31;       // l within tile
        const int cr = tid >> 5;       // 0..15
        const float* src = in + ((size_t)b * C) * L + l0 + ll;
        #pragma unroll
        for (int i = 0; i < 4; ++i) {
            const int c = cr + i * 16;
            tile[c * PITCH + ll] = src[(size_t)c * L];
        }
    }
    __syncthreads();

    // ---- Compute + store: thread owns (ll, c4) -> 4 consecutive channels
    const int c4 = tid & 15;           // channel group 0..15
    const int ll = tid >> 4;           // l within tile 0..31
    const int c  = c4 * 4;
    const int l  = l0 + ll;

    const float x0 = tile[(c + 0) * PITCH + ll];
    const float x1 = tile[(c + 1) * PITCH + ll];
    const float x2 = tile[(c + 2) * PITCH + ll];
    const float x3 = tile[(c + 3) * PITCH + ll];

    float v0 = 0.f, v1 = 0.f, v2 = 0.f, v3 = 0.f;

    // Output [B, T, L, C]: base at t=0, stride L*C floats per timestep.
    float4* outp = reinterpret_cast<float4*>(
        out + ((size_t)b * T * L + l) * C + c);
    constexpr size_t strideT4 = (size_t)L * C / 4;

    #pragma unroll
    for (int t = 0; t < T; ++t) {
        // v = v + (x - v)/tau, tau = 2 (mul by 0.5 is exact)
        v0 += (x0 - v0) * 0.5f;
        v1 += (x1 - v1) * 0.5f;
        v2 += (x2 - v2) * 0.5f;
        v3 += (x3 - v3) * 0.5f;

        const float s0 = (v0 >= 1.0f) ? 1.0f : 0.0f;
        const float s1 = (v1 >= 1.0f) ? 1.0f : 0.0f;
        const float s2 = (v2 >= 1.0f) ? 1.0f : 0.0f;
        const float s3 = (v3 >= 1.0f) ? 1.0f : 0.0f;

        v0 = (s0 != 0.0f) ? 0.0f : v0;
        v1 = (s1 != 0.0f) ? 0.0f : v1;
        v2 = (s2 != 0.0f) ? 0.0f : v2;
        v3 = (s3 != 0.0f) ? 0.0f : v3;

        outp[(size_t)t * strideT4] = make_float4(s0, s1, s2, s3);
    }
}

extern "C" void kernel_launch(void* const* d_in, const int* in_sizes, int n_in,
                              void* d_out, int out_size) {
    (void)in_sizes; (void)n_in; (void)out_size;
    const float* in = (const float*)d_in[0];
    float* out = (float*)d_out;

    const int blocks = B * (L / LT);   // 1024
    lif_repeat_encoder_kernel<<<blocks, THREADS>>>(in, out);
}

// round 7
// speedup vs baseline: 1.0854x; 1.0486x over previous
#include <cuda_runtime.h>
#include <cuda_bf16.h>
#include <cstdint>

// RepeatEncoder: LIF spiking neuron over T=32 repeated presentations of the
// same frame. Input [B=64, C=64, L=512] fp32 -> output [B, T=32, L, C] fp32.
//
// Per (b,l,c): x = in[b,c,l]; v=0; for t in 0..31:
//   v += (x - v)*0.5;  s = (v >= 1);  v = s ? 0 : v;  out[b,t,l,c] = s
//
// Steady-state DRAM-write (dirty-eviction) bound: the 256 MB output stream
// must drain through L2 to HBM on every graph replay. R6 change: stores use
// st.global.cs (evict-first streaming hint) so written lines leave L2
// promptly instead of piling up ~50 MB of dirty state that back-pressures
// the next replay. Input staging via smem (coalesced) unchanged from R5.

namespace {
constexpr int B  = 64;
constexpr int C  = 64;
constexpr int L  = 512;
constexpr int T  = 32;
constexpr int LT = 32;                 // l-tile per block
constexpr int THREADS = 512;           // = LT * (C/4) compute units
constexpr int PITCH = LT + 1;          // smem pitch (33 floats) to limit conflicts
}

__global__ void __launch_bounds__(THREADS)
lif_repeat_encoder_kernel(const float* __restrict__ in, float* __restrict__ out) {
    __shared__ float tile[C * PITCH];  // tile[c][ll], pitch 33

    const int tid = threadIdx.x;
    const int bid = blockIdx.x;        // 0 .. B*(L/LT)-1 = 1023
    const int b   = bid >> 4;          // bid / (L/LT)
    const int l0  = (bid & 15) << 5;   // (bid % 16) * 32

    // ---- Coalesced load: input [B, C, L], this block needs [b, 0:64, l0:l0+32]
    // 4 iterations x 512 threads; each warp loads 32 consecutive floats (128B).
    {
        const int ll = tid & 31;       // l within tile
        const int cr = tid >> 5;       // 0..15
        const float* src = in + ((size_t)b * C) * L + l0 + ll;
        #pragma unroll
        for (int i = 0; i < 4; ++i) {
            const int c = cr + i * 16;
            tile[c * PITCH + ll] = src[(size_t)c * L];
        }
    }
    __syncthreads();

    // ---- Compute + store: thread owns (ll, c4) -> 4 consecutive channels
    const int c4 = tid & 15;           // channel group 0..15
    const int ll = tid >> 4;           // l within tile 0..31
    const int c  = c4 * 4;
    const int l  = l0 + ll;

    const float x0 = tile[(c + 0) * PITCH + ll];
    const float x1 = tile[(c + 1) * PITCH + ll];
    const float x2 = tile[(c + 2) * PITCH + ll];
    const float x3 = tile[(c + 3) * PITCH + ll];

    float v0 = 0.f, v1 = 0.f, v2 = 0.f, v3 = 0.f;

    // Output [B, T, L, C]: base at t=0, stride L*C floats per timestep.
    float4* outp = reinterpret_cast<float4*>(
        out + ((size_t)b * T * L + l) * C + c);
    constexpr size_t strideT4 = (size_t)L * C / 4;

    #pragma unroll
    for (int t = 0; t < T; ++t) {
        // v = v + (x - v)/tau, tau = 2 (mul by 0.5 is exact)
        v0 += (x0 - v0) * 0.5f;
        v1 += (x1 - v1) * 0.5f;
        v2 += (x2 - v2) * 0.5f;
        v3 += (x3 - v3) * 0.5f;

        const float s0 = (v0 >= 1.0f) ? 1.0f : 0.0f;
        const float s1 = (v1 >= 1.0f) ? 1.0f : 0.0f;
        const float s2 = (v2 >= 1.0f) ? 1.0f : 0.0f;
        const float s3 = (v3 >= 1.0f) ? 1.0f : 0.0f;

        v0 = (s0 != 0.0f) ? 0.0f : v0;
        v1 = (s1 != 0.0f) ? 0.0f : v1;
        v2 = (s2 != 0.0f) ? 0.0f : v2;
        v3 = (s3 != 0.0f) ? 0.0f : v3;

        // Streaming store: evict-first, this data is never re-read on-chip.
        __stcs(outp + (size_t)t * strideT4, make_float4(s0, s1, s2, s3));
    }
}

extern "C" void kernel_launch(void* const* d_in, const int* in_sizes, int n_in,
                              void* d_out, int out_size) {
    (void)in_sizes; (void)n_in; (void)out_size;
    const float* in = (const float*)d_in[0];
    float* out = (float*)d_out;

    const int blocks = B * (L / LT);   // 1024
    lif_repeat_encoder_kernel<<<blocks, THREADS>>>(in, out);
}

// round 8
// speedup vs baseline: 1.0862x; 1.0007x over previous
#include <cuda_runtime.h>
#include <cuda_bf16.h>
#include <cstdint>

// RepeatEncoder: LIF spiking neuron over T=32 repeated presentations of the
// same frame. Input [B=64, C=64, L=512] fp32 -> output [B, T=32, L, C] fp32.
//
// Per (b,l,c): x = in[b,c,l]; v=0; for t in 0..31:
//   v += (x - v)*0.5;  s = (v >= 1);  v = s ? 0 : v;  out[b,t,l,c] = s
//
// Steady-state DRAM-write (dirty-eviction) bound: the 256 MB output stream
// must drain through L2 to HBM on every graph replay. R6 change: stores use
// st.global.cs (evict-first streaming hint) so written lines leave L2
// promptly instead of piling up ~50 MB of dirty state that back-pressures
// the next replay. Input staging via smem (coalesced) unchanged from R5.

namespace {
constexpr int B  = 64;
constexpr int C  = 64;
constexpr int L  = 512;
constexpr int T  = 32;
constexpr int LT = 32;                 // l-tile per block
constexpr int THREADS = 512;           // = LT * (C/4) compute units
constexpr int PITCH = LT + 1;          // smem pitch (33 floats) to limit conflicts
}

__global__ void __launch_bounds__(THREADS)
lif_repeat_encoder_kernel(const float* __restrict__ in, float* __restrict__ out) {
    __shared__ float tile[C * PITCH];  // tile[c][ll], pitch 33

    const int tid = threadIdx.x;
    const int bid = blockIdx.x;        // 0 .. B*(L/LT)-1 = 1023
    const int b   = bid >> 4;          // bid / (L/LT)
    const int l0  = (bid & 15) << 5;   // (bid % 16) * 32

    // ---- Coalesced load: input [B, C, L], this block needs [b, 0:64, l0:l0+32]
    // 4 iterations x 512 threads; each warp loads 32 consecutive floats (128B).
    {
        const int ll = tid & 31;       // l within tile
        const int cr = tid >> 5;       // 0..15
        const float* src = in + ((size_t)b * C) * L + l0 + ll;
        #pragma unroll
        for (int i = 0; i < 4; ++i) {
            const int c = cr + i * 16;
            tile[c * PITCH + ll] = src[(size_t)c * L];
        }
    }
    __syncthreads();

    // ---- Compute + store: thread owns (ll, c4) -> 4 consecutive channels
    const int c4 = tid & 15;           // channel group 0..15
    const int ll = tid >> 4;           // l within tile 0..31
    const int c  = c4 * 4;
    const int l  = l0 + ll;

    const float x0 = tile[(c + 0) * PITCH + ll];
    const float x1 = tile[(c + 1) * PITCH + ll];
    const float x2 = tile[(c + 2) * PITCH + ll];
    const float x3 = tile[(c + 3) * PITCH + ll];

    float v0 = 0.f, v1 = 0.f, v2 = 0.f, v3 = 0.f;

    // Output [B, T, L, C]: base at t=0, stride L*C floats per timestep.
    float4* outp = reinterpret_cast<float4*>(
        out + ((size_t)b * T * L + l) * C + c);
    constexpr size_t strideT4 = (size_t)L * C / 4;

    #pragma unroll
    for (int t = 0; t < T; ++t) {
        // v = v + (x - v)/tau, tau = 2 (mul by 0.5 is exact)
        v0 += (x0 - v0) * 0.5f;
        v1 += (x1 - v1) * 0.5f;
        v2 += (x2 - v2) * 0.5f;
        v3 += (x3 - v3) * 0.5f;

        const float s0 = (v0 >= 1.0f) ? 1.0f : 0.0f;
        const float s1 = (v1 >= 1.0f) ? 1.0f : 0.0f;
        const float s2 = (v2 >= 1.0f) ? 1.0f : 0.0f;
        const float s3 = (v3 >= 1.0f) ? 1.0f : 0.0f;

        v0 = (s0 != 0.0f) ? 0.0f : v0;
        v1 = (s1 != 0.0f) ? 0.0f : v1;
        v2 = (s2 != 0.0f) ? 0.0f : v2;
        v3 = (s3 != 0.0f) ? 0.0f : v3;

        // Streaming store: evict-first, this data is never re-read on-chip.
        __stcs(outp + (size_t)t * strideT4, make_float4(s0, s1, s2, s3));
    }
}

extern "C" void kernel_launch(void* const* d_in, const int* in_sizes, int n_in,
                              void* d_out, int out_size) {
    (void)in_sizes; (void)n_in; (void)out_size;
    const float* in = (const float*)d_in[0];
    float* out = (float*)d_out;

    const int blocks = B * (L / LT);   // 1024
    lif_repeat_encoder_kernel<<<blocks, THREADS>>>(in, out);
}